// round 8
// baseline (speedup 1.0000x reference)
#include <cuda_runtime.h>
#include <cuda_bf16.h>
#include <math.h>

// ---------------------------------------------------------------------------
// Seq2Seq LSTM (B=64, S=1024, T=512, H=512, D_IN=D_OUT=32), fp32.
// Persistent kernel: 128 CTAs x 512 threads, flag-based grid barrier.
// Inner GEMM uses packed fma.rn.f32x2 (FFMA2): 2 MACs/inst, pairing over k.
// Encoder phases merged (L1(t-1)+L0(t) in one barrier). Decoder unmerged.
// Decoder feedback GEMM folded into precomputed gM = dec_Wih0 @ out_W.
// ---------------------------------------------------------------------------

#define NB   128
#define NT   512
#define B_    64
#define H_    512
#define G4   2048
#define DIN   32
#define SLEN 1024
#define TLEN  512

#define BUFW 12                       // floats per batch row in stage buffer
#define BUFSZ (64 * BUFW)             // 768 floats per warp
#define REDBASE (16 * BUFSZ)          // 12288 floats
#define RROW  1042                    // unmerged reduction row stride
#define RROW2 520                     // merged reduction row stride (bank-exact)
#define SMEM_FLOATS (REDBASE + 16 * RROW)     // >= REDBASE + 32*RROW2
#define SMEM_BYTES  (SMEM_FLOATS * 4)         // 115840 B

typedef unsigned long long u64;

struct P {
    const float *src;
    const float *eWih0, *eWhh0, *ebih0, *ebhh0;
    const float *eWih1, *eWhh1, *ebih1, *ebhh1;
    const float *dWih0, *dWhh0, *dbih0, *dbhh0;
    const float *dWih1, *dWhh1, *dbih1, *dbhh1;
    const float *outW, *outB;
    float *out;
};

// ---- persistent state (device globals; allocation-free scratch) ----
__device__ float gH0[2][B_ * H_];
__device__ float gH1[2][B_ * H_];
__device__ float gC0[B_ * H_];
__device__ float gC1[B_ * H_];
__device__ float gM[G4 * H_];      // dec_Wih0 @ out_W   [2048 x 512]
__device__ float gB2[G4];          // dec_Wih0 @ out_b
__device__ unsigned gFlag[NB];     // monotonic per-CTA arrival counters
__device__ volatile unsigned g_gen = 0;

__device__ __forceinline__ void grid_bar(unsigned &bgen) {
    __threadfence();
    __syncthreads();
    bgen++;
    if (blockIdx.x == 0) {
        if (threadIdx.x > 0 && threadIdx.x < NB) {
            volatile unsigned* f = gFlag + threadIdx.x;
            while (*f < bgen) __nanosleep(16);
        }
        __syncthreads();
        if (threadIdx.x == 0) { __threadfence(); g_gen = bgen; }
    } else {
        if (threadIdx.x == 0) {
            ((volatile unsigned*)gFlag)[blockIdx.x] = bgen;
            while (g_gen < bgen) __nanosleep(16);
        }
        __syncthreads();
    }
}

__device__ __forceinline__ float sigm(float x) { return 1.0f / (1.0f + expf(-x)); }

// packed f32x2 fma: d.lo += a.lo*b.lo, d.hi += a.hi*b.hi
__device__ __forceinline__ void fma2(u64 &d, u64 a, u64 b) {
    asm("fma.rn.f32x2 %0, %1, %2, %0;" : "+l"(d) : "l"(a), "l"(b));
}
__device__ __forceinline__ float f2sum(u64 v) {
    float lo, hi;
    asm("mov.b64 {%0,%1}, %2;" : "=f"(lo), "=f"(hi) : "l"(v));
    return lo + hi;
}
// 16B read-only global load as two f32x2 words
__device__ __forceinline__ ulonglong2 ldgnc2(const float* p) {
    ulonglong2 v;
    asm("ld.global.nc.v2.u64 {%0,%1}, [%2];" : "=l"(v.x), "=l"(v.y) : "l"(p));
    return v;
}
__device__ __forceinline__ u64 ldgnc1(const float* p) {
    u64 v;
    asm("ld.global.nc.u64 %0, [%1];" : "=l"(v) : "l"(p));
    return v;
}

// K=512 term: warp accumulates nch chunks of 8 k starting at kbase into
// acc2[4 rows][8 batches] (f32x2, paired over k). Wrow0 row stride 512.
// x: [64 rows, stride ld]. Register-prefetched staging, warp-private buffer.
__device__ __forceinline__ void term512(
    const float* __restrict__ x, int ld, const float* __restrict__ Wrow0,
    bool cg, int kbase, int nch, int lane, int bq, u64 acc2[4][8], float* buf)
{
    const int j0 = lane, j1 = 32 + lane, j2 = 64 + lane, j3 = 96 + lane;
    const int b0 = j0 >> 1, b1 = j1 >> 1, b2_ = j2 >> 1, b3 = j3 >> 1;
    const int q0 = (j0 & 1) << 2, q1 = (j1 & 1) << 2, q2 = (j2 & 1) << 2, q3 = (j3 & 1) << 2;

    float4 pf0, pf1, pf2, pf3;
    {
        const float* g0 = x + b0 * ld + kbase + q0;
        const float* g1 = x + b1 * ld + kbase + q1;
        const float* g2 = x + b2_ * ld + kbase + q2;
        const float* g3 = x + b3 * ld + kbase + q3;
        if (cg) { pf0 = __ldcg((const float4*)g0); pf1 = __ldcg((const float4*)g1);
                  pf2 = __ldcg((const float4*)g2); pf3 = __ldcg((const float4*)g3); }
        else    { pf0 = __ldg((const float4*)g0);  pf1 = __ldg((const float4*)g1);
                  pf2 = __ldg((const float4*)g2);  pf3 = __ldg((const float4*)g3); }
    }
    for (int c = 0; c < nch; c++) {
        __syncwarp();                      // prior chunk fully consumed
        *(float4*)(buf + b0 * BUFW + q0) = pf0;
        *(float4*)(buf + b1 * BUFW + q1) = pf1;
        *(float4*)(buf + b2_ * BUFW + q2) = pf2;
        *(float4*)(buf + b3 * BUFW + q3) = pf3;
        if (c < nch - 1) {                 // prefetch next chunk under compute
            const int ko = kbase + (c + 1) * 8;
            const float* g0 = x + b0 * ld + ko + q0;
            const float* g1 = x + b1 * ld + ko + q1;
            const float* g2 = x + b2_ * ld + ko + q2;
            const float* g3 = x + b3 * ld + ko + q3;
            if (cg) { pf0 = __ldcg((const float4*)g0); pf1 = __ldcg((const float4*)g1);
                      pf2 = __ldcg((const float4*)g2); pf3 = __ldcg((const float4*)g3); }
            else    { pf0 = __ldg((const float4*)g0);  pf1 = __ldg((const float4*)g1);
                      pf2 = __ldg((const float4*)g2);  pf3 = __ldg((const float4*)g3); }
        }
        __syncwarp();                      // staged data visible
        const float* wb = Wrow0 + kbase + c * 8;
        const float* hb = buf + bq * BUFW;
        #pragma unroll
        for (int kk = 0; kk < 8; kk += 4) {
            ulonglong2 w0 = ldgnc2(wb + 0 * H_ + kk);
            ulonglong2 w1 = ldgnc2(wb + 1 * H_ + kk);
            ulonglong2 w2 = ldgnc2(wb + 2 * H_ + kk);
            ulonglong2 w3 = ldgnc2(wb + 3 * H_ + kk);
            #pragma unroll
            for (int m = 0; m < 8; m++) {
                ulonglong2 hv = *(const ulonglong2*)(hb + m * (8 * BUFW) + kk);
                fma2(acc2[0][m], w0.x, hv.x); fma2(acc2[0][m], w0.y, hv.y);
                fma2(acc2[1][m], w1.x, hv.x); fma2(acc2[1][m], w1.y, hv.y);
                fma2(acc2[2][m], w2.x, hv.x); fma2(acc2[2][m], w2.y, hv.y);
                fma2(acc2[3][m], w3.x, hv.x); fma2(acc2[3][m], w3.y, hv.y);
            }
        }
    }
    __syncwarp();
}

// K=32 term, 16 segments (unmerged): warp takes 2 k columns.
__device__ __forceinline__ void term32w2(
    const float* __restrict__ x, int ld, const float* __restrict__ Wrow0,
    int seg, int lane, int bq, u64 acc2[4][8], float* buf)
{
    const int kbase = seg * 2;
    __syncwarp();
    #pragma unroll
    for (int i = 0; i < 2; i++) {
        int b = lane + (i << 5);
        float2 v = __ldg((const float2*)(x + b * ld + kbase));
        *(float2*)(buf + b * BUFW) = v;
    }
    __syncwarp();
    u64 w0 = ldgnc1(Wrow0 + 0 * DIN + kbase);
    u64 w1 = ldgnc1(Wrow0 + 1 * DIN + kbase);
    u64 w2 = ldgnc1(Wrow0 + 2 * DIN + kbase);
    u64 w3 = ldgnc1(Wrow0 + 3 * DIN + kbase);
    #pragma unroll
    for (int m = 0; m < 8; m++) {
        u64 hv = *(const u64*)(buf + ((m << 3) + bq) * BUFW);
        fma2(acc2[0][m], w0, hv);
        fma2(acc2[1][m], w1, hv);
        fma2(acc2[2][m], w2, hv);
        fma2(acc2[3][m], w3, hv);
    }
    __syncwarp();
}

// K=32 term, 8 segments (merged encoder): warp takes 4 k columns.
__device__ __forceinline__ void term32w4(
    const float* __restrict__ x, int ld, const float* __restrict__ Wrow0,
    int seg, int lane, int bq, u64 acc2[4][8], float* buf)
{
    const int kbase = seg * 4;
    __syncwarp();
    #pragma unroll
    for (int i = 0; i < 2; i++) {
        int b = lane + (i << 5);
        float4 v = __ldg((const float4*)(x + b * ld + kbase));
        *(float4*)(buf + b * BUFW) = v;
    }
    __syncwarp();
    ulonglong2 w0 = ldgnc2(Wrow0 + 0 * DIN + kbase);
    ulonglong2 w1 = ldgnc2(Wrow0 + 1 * DIN + kbase);
    ulonglong2 w2 = ldgnc2(Wrow0 + 2 * DIN + kbase);
    ulonglong2 w3 = ldgnc2(Wrow0 + 3 * DIN + kbase);
    #pragma unroll
    for (int m = 0; m < 8; m++) {
        ulonglong2 hv = *(const ulonglong2*)(buf + ((m << 3) + bq) * BUFW);
        fma2(acc2[0][m], w0.x, hv.x); fma2(acc2[0][m], w0.y, hv.y);
        fma2(acc2[1][m], w1.x, hv.x); fma2(acc2[1][m], w1.y, hv.y);
        fma2(acc2[2][m], w2.x, hv.x); fma2(acc2[2][m], w2.y, hv.y);
        fma2(acc2[3][m], w3.x, hv.x); fma2(acc2[3][m], w3.y, hv.y);
    }
    __syncwarp();
}

// ---- unmerged LSTM phase (decoder + encoder prologue/epilogue) ----
// 16 warps, 32-k slice each. Term A: KA in {0,32,512}; term B: K=512 (.cg).
__device__ __forceinline__ void lstm_phase(
    const float* xA, int ldA, const float* __restrict__ WA, int KA, bool cgA,
    const float* xB, const float* __restrict__ WB,
    const float* __restrict__ bih, const float* __restrict__ bhh,
    const float* __restrict__ b2,
    float* __restrict__ cst, float* __restrict__ hout, float* smem)
{
    const int tid  = threadIdx.x;
    const int w    = tid >> 5, lane = tid & 31;
    const int gate = lane >> 3, bq = lane & 7;
    float* buf = smem + w * BUFSZ;
    float* red = smem + REDBASE;

    u64 acc2[4][8];
    #pragma unroll
    for (int r = 0; r < 4; r++)
        #pragma unroll
        for (int m = 0; m < 8; m++) acc2[r][m] = 0ULL;

    const size_t rowbase = (size_t)((gate << 9) + (blockIdx.x << 2));
    if (KA == 512)     term512(xA, ldA, WA + rowbase * H_, cgA, w * 32, 4, lane, bq, acc2, buf);
    else if (KA == 32) term32w2(xA, ldA, WA + rowbase * DIN, w, lane, bq, acc2, buf);
    term512(xB, H_, WB + rowbase * H_, true, w * 32, 4, lane, bq, acc2, buf);

    #pragma unroll
    for (int rr = 0; rr < 4; rr++)
        #pragma unroll
        for (int m = 0; m < 8; m++)
            red[((gate << 2) + rr) * RROW + (w << 6) + (m << 3) + bq] = f2sum(acc2[rr][m]);
    __syncthreads();

    if (tid < 256) {
        const int u = tid & 3, b = tid >> 2;
        const int ug = (blockIdx.x << 2) + u;
        float g4v[4];
        #pragma unroll
        for (int g = 0; g < 4; g++) {
            float s = 0.0f;
            #pragma unroll
            for (int s16 = 0; s16 < 16; s16++)
                s += red[((g << 2) + u) * RROW + (s16 << 6) + b];
            int r = (g << 9) + ug;
            s += __ldg(bih + r) + __ldg(bhh + r);
            if (b2) s += __ldg(b2 + r);
            g4v[g] = s;
        }
        const int idx = (b << 9) + ug;
        float cp = __ldcg(cst + idx);
        float cn = sigm(g4v[1]) * cp + sigm(g4v[0]) * tanhf(g4v[2]);
        __stcg(cst + idx, cn);
        __stcg(hout + idx, sigm(g4v[3]) * tanhf(cn));
    }
}

// ---- merged encoder phase t (1..1023): computes L1(t-1) AND L0(t) ----
// Warps 0-7: L0 tile (src(t) + h0(t-1)@eWhh0), 64-k slices.
// Warps 8-15: L1 tile (h0(t-1)@eWih1 + h1(t-2)@eWhh1), 64-k slices.
__device__ __forceinline__ void enc_merged(const P& p, int t, float* smem)
{
    const int tid  = threadIdx.x;
    const int w    = tid >> 5, lane = tid & 31;
    const int grp  = w >> 3, seg = w & 7;
    const int gate = lane >> 3, bq = lane & 7;
    float* buf = smem + w * BUFSZ;
    float* red = smem + REDBASE;

    u64 acc2[4][8];
    #pragma unroll
    for (int r = 0; r < 4; r++)
        #pragma unroll
        for (int m = 0; m < 8; m++) acc2[r][m] = 0ULL;

    const size_t rowbase = (size_t)((gate << 9) + (blockIdx.x << 2));
    const float* h0prev = gH0[(t - 1) & 1];     // h0(t-1)
    if (grp == 0) {
        term32w4(p.src + t * DIN, SLEN * DIN, p.eWih0 + rowbase * DIN,
                 seg, lane, bq, acc2, buf);
        term512(h0prev, H_, p.eWhh0 + rowbase * H_, true, seg * 64, 8, lane, bq, acc2, buf);
    } else {
        const float* h1prev2 = gH1[t & 1];      // h1(t-2) lives in buf t&1
        term512(h0prev,  H_, p.eWih1 + rowbase * H_, true, seg * 64, 8, lane, bq, acc2, buf);
        term512(h1prev2, H_, p.eWhh1 + rowbase * H_, true, seg * 64, 8, lane, bq, acc2, buf);
    }

    #pragma unroll
    for (int rr = 0; rr < 4; rr++)
        #pragma unroll
        for (int m = 0; m < 8; m++)
            red[((grp << 4) + (gate << 2) + rr) * RROW2 + (seg << 6) + (m << 3) + bq] = f2sum(acc2[rr][m]);
    __syncthreads();

    // finalize: 512 threads, one (layer, b, u) each
    {
        const int L = tid >> 8, rem = tid & 255;
        const int u = rem & 3, b = rem >> 2;
        const int ug = (blockIdx.x << 2) + u;
        const float* bih = L ? p.ebih1 : p.ebih0;
        const float* bhh = L ? p.ebhh1 : p.ebhh0;
        float g4v[4];
        #pragma unroll
        for (int g = 0; g < 4; g++) {
            float s = 0.0f;
            #pragma unroll
            for (int s8 = 0; s8 < 8; s8++)
                s += red[((L << 4) + (g << 2) + u) * RROW2 + (s8 << 6) + b];
            int r = (g << 9) + ug;
            s += __ldg(bih + r) + __ldg(bhh + r);
            g4v[g] = s;
        }
        float* cst  = L ? gC1 : gC0;
        float* hout = L ? gH1[(t - 1) & 1] : gH0[t & 1];
        const int idx = (b << 9) + ug;
        float cp = __ldcg(cst + idx);
        float cn = sigm(g4v[1]) * cp + sigm(g4v[0]) * tanhf(g4v[2]);
        __stcg(cst + idx, cn);
        __stcg(hout + idx, sigm(g4v[3]) * tanhf(cn));
    }
}

// pred(t) = h1 @ out_W.T + out_b -> d_out[:, t, :].
// Spread over ALL CTAs: 64 threads/CTA, 16 outputs/CTA.
__device__ __forceinline__ void do_pred(const P& p, const float* __restrict__ h1, int t)
{
    if (threadIdx.x >= 64) return;
    int g = (blockIdx.x << 6) + threadIdx.x;   // 0..8191
    int oid = g >> 2, part = g & 3;            // 2048 outputs, K split by 4
    int b = oid >> 5, j = oid & 31;
    const float* hr = h1 + (b << 9) + (part << 7);
    const float* wr = p.outW + (j << 9) + (part << 7);
    float s = 0.0f;
    #pragma unroll
    for (int k = 0; k < 128; k += 4) {
        float4 hv = __ldcg((const float4*)(hr + k));
        float4 wv = __ldg ((const float4*)(wr + k));
        s = fmaf(hv.x, wv.x, fmaf(hv.y, wv.y, fmaf(hv.z, wv.z, fmaf(hv.w, wv.w, s))));
    }
    s += __shfl_xor_sync(0xffffffffu, s, 1);
    s += __shfl_xor_sync(0xffffffffu, s, 2);
    if (part == 0)
        p.out[((long)b << 14) + (t << 5) + j] = s + __ldg(p.outB + j);
}

__global__ void __launch_bounds__(NT, 1) seq2seq_kernel(P p)
{
    extern __shared__ float smem[];
    const int gt = blockIdx.x * NT + threadIdx.x;   // 0..65535
    unsigned bgen = g_gen;                          // monotonic barrier epoch

    // ---- zero init: h(-1) lives in buffer 1 ----
    if (gt < B_ * H_) {
        __stcg(&gH0[1][gt], 0.0f);
        __stcg(&gH1[1][gt], 0.0f);
        __stcg(&gC0[gt],    0.0f);
        __stcg(&gC1[gt],    0.0f);
    }
    grid_bar(bgen);

    // ---- precompute M = dec_Wih0 @ out_W, b2 = dec_Wih0 @ out_b ----
    for (int o = gt; o < G4 * H_; o += NB * NT) {
        int rr = o >> 9, hc = o & 511;
        const float* wr = p.dWih0 + rr * DIN;
        const float* oc = p.outW + hc;
        float s = 0.0f;
        #pragma unroll
        for (int j = 0; j < DIN; j++) s = fmaf(__ldg(wr + j), __ldg(oc + j * H_), s);
        __stcg(&gM[o], s);
    }
    if (gt < G4) {
        const float* wr = p.dWih0 + gt * DIN;
        float s = 0.0f;
        #pragma unroll
        for (int j = 0; j < DIN; j++) s = fmaf(__ldg(wr + j), __ldg(p.outB + j), s);
        __stcg(&gB2[gt], s);
    }
    grid_bar(bgen);

    // ---- encoder ----
    // prologue: L0(0)   (reads h0(-1)=zeros in buf 1, writes h0(0) -> buf 0)
    lstm_phase(p.src, SLEN * DIN, p.eWih0, DIN, false,
               gH0[1], p.eWhh0,
               p.ebih0, p.ebhh0, nullptr, gC0, gH0[0], smem);
    grid_bar(bgen);
    // merged main loop: phase t computes L1(t-1) and L0(t)
    for (int t = 1; t < SLEN; t++) {
        enc_merged(p, t, smem);
        grid_bar(bgen);
    }
    // epilogue: L1(1023)  (h0(1023) in buf 1, h1(1022) in buf 0 -> h1(1023) buf 1)
    lstm_phase(gH0[1], H_, p.eWih1, H_, true,
               gH1[0], p.eWhh1,
               p.ebih1, p.ebhh1, nullptr, gC1, gH1[1], smem);
    grid_bar(bgen);

    // ---- decoder: 512 steps x 2 phases (+ pred side job, all CTAs) ----
    // h_dec(t) in buf t&1; h_dec(-1) = encoder finals in buf 1.
    for (int t = 0; t < TLEN; t++) {
        const int rp = (t - 1) & 1, wp = t & 1;
        lstm_phase(t ? gH1[rp] : nullptr, H_, gM, t ? H_ : 0, true,
                   gH0[rp], p.dWhh0,
                   p.dbih0, p.dbhh0, t ? gB2 : nullptr, gC0, gH0[wp], smem);
        if (t > 0) do_pred(p, gH1[rp], t - 1);
        grid_bar(bgen);
        lstm_phase(gH0[wp], H_, p.dWih1, H_, true,
                   gH1[rp], p.dWhh1,
                   p.dbih1, p.dbhh1, nullptr, gC1, gH1[wp], smem);
        grid_bar(bgen);
    }
    // final pred for t = TLEN-1 (h1(511) in buf 1)
    do_pred(p, gH1[1], TLEN - 1);
}

extern "C" void kernel_launch(void* const* d_in, const int* in_sizes, int n_in,
                              void* d_out, int out_size)
{
    const int o = (in_sizes[1] < 100) ? 1 : 0;   // skip target_length scalar if present

    P p;
    p.src   = (const float*)d_in[0];
    p.eWih0 = (const float*)d_in[1 + o];
    p.eWhh0 = (const float*)d_in[2 + o];
    p.ebih0 = (const float*)d_in[3 + o];
    p.ebhh0 = (const float*)d_in[4 + o];
    p.eWih1 = (const float*)d_in[5 + o];
    p.eWhh1 = (const float*)d_in[6 + o];
    p.ebih1 = (const float*)d_in[7 + o];
    p.ebhh1 = (const float*)d_in[8 + o];
    p.dWih0 = (const float*)d_in[9 + o];
    p.dWhh0 = (const float*)d_in[10 + o];
    p.dbih0 = (const float*)d_in[11 + o];
    p.dbhh0 = (const float*)d_in[12 + o];
    p.dWih1 = (const float*)d_in[13 + o];
    p.dWhh1 = (const float*)d_in[14 + o];
    p.dbih1 = (const float*)d_in[15 + o];
    p.dbhh1 = (const float*)d_in[16 + o];
    p.outW  = (const float*)d_in[17 + o];
    p.outB  = (const float*)d_in[18 + o];
    p.out   = (float*)d_out;

    cudaFuncSetAttribute(seq2seq_kernel,
                         cudaFuncAttributeMaxDynamicSharedMemorySize, SMEM_BYTES);
    seq2seq_kernel<<<NB, NT, SMEM_BYTES>>>(p);
}